// round 16
// baseline (speedup 1.0000x reference)
#include <cuda_runtime.h>
#include <cuda_bf16.h>
#include <math.h>
#include <stdint.h>

#define N 8192
#define D 64
#define H1 128
#define H2 64
#define KNB 16            // kept neighbors per row (rank 0 = self, dropped)
#define E (N * KNB)       // 131072 fixed edge slots, src(e) = e >> 4
#define CAP 512           // candidate slots per row
#define CAND_THR 0.25f    // prefilter threshold on approx sims (17th max ~ 0.36)

// ---------------- device scratch (no allocations allowed) ----------------
__device__ unsigned long long g_cand[(size_t)N * CAP];  // 32 MB candidate keys
__device__ int   g_ccnt[N];
__device__ int   g_bad[N];
__device__ float g_ninv[N];                // 1/||x_i||
__device__ float g_dinv[N];
__device__ int   g_edst[E];
__device__ float g_ew[E];
__device__ int   g_cnt[N];
__device__ int   g_fill[N];
__device__ int   g_off[N + 1];
__device__ int   g_inc[E];                 // CSR-by-dst edge ids (sorted per bucket)
__device__ float g_h1[(size_t)N * H1];
__device__ float g_y1[(size_t)N * H1];
__device__ float g_h2[(size_t)N * H2];
__device__ float g_y2[(size_t)N * H2];
// bf16x3 split of x (hi + mid + lo reconstructs fp32 to ~2^-25)
__device__ __nv_bfloat16 g_xhi[(size_t)N * D];
__device__ __nv_bfloat16 g_xmid[(size_t)N * D];
__device__ __nv_bfloat16 g_xlo[(size_t)N * D];

// order-preserving float <-> uint key (ascending)
__device__ __forceinline__ unsigned okey(float v) {
    unsigned u = __float_as_uint(v);
    return u ^ (((unsigned)((int)u >> 31)) | 0x80000000u);
}
__device__ __forceinline__ float iokey(unsigned u) {
    return __uint_as_float(u ^ ((~((unsigned)((int)u >> 31))) | 0x80000000u));
}

__device__ __forceinline__ uint32_t smem_u32(const void* p) {
    uint32_t a;
    asm("{ .reg .u64 t; cvta.to.shared.u64 t, %1; cvt.u32.u64 %0, t; }" : "=r"(a) : "l"(p));
    return a;
}
__device__ __forceinline__ uint32_t swz128(uint32_t off) {
    return off ^ ((off >> 3) & 0x70);
}
__device__ __forceinline__ void ldm4(uint32_t* r, uint32_t addr) {
    asm volatile("ldmatrix.sync.aligned.m8n8.x4.shared.b16 {%0,%1,%2,%3}, [%4];"
                 : "=r"(r[0]), "=r"(r[1]), "=r"(r[2]), "=r"(r[3]) : "r"(addr));
}
__device__ __forceinline__ void mma_bf16(float* c, const uint32_t* a, const uint32_t* b) {
    asm volatile("mma.sync.aligned.m16n8k16.row.col.f32.bf16.bf16.f32 "
                 "{%0,%1,%2,%3}, {%4,%5,%6,%7}, {%8,%9}, {%0,%1,%2,%3};"
                 : "+f"(c[0]), "+f"(c[1]), "+f"(c[2]), "+f"(c[3])
                 : "r"(a[0]), "r"(a[1]), "r"(a[2]), "r"(a[3]), "r"(b[0]), "r"(b[1]));
}

// ---------------- fused norms + init + bf16x3 split ----------------
__global__ void norm_init_kernel(const float* __restrict__ x,
                                 float* o_ei0, float* o_ei1, float* o_ew) {
    int gi = blockIdx.x * blockDim.x + threadIdx.x;
    if (gi < N) {
        g_ccnt[gi] = 0;
        g_bad[gi]  = 0;
        g_cnt[gi]  = 0;
        g_fill[gi] = 0;
        if (o_ei0) {
            size_t p = (size_t)E + gi;
            o_ei0[p] = (float)gi;
            o_ei1[p] = (float)gi;
            o_ew[p]  = 1.0f;
        }
    }
    int warp = gi >> 5;
    int lane = threadIdx.x & 31;
    if (warp >= N) return;
    const float* row = x + (size_t)warp * D;
    float a = row[lane], b = row[lane + 32];

    size_t i0 = (size_t)warp * D + lane;
    size_t i1 = i0 + 32;
    {
        __nv_bfloat16 h = __float2bfloat16(a);
        float r1 = a - __bfloat162float(h);
        __nv_bfloat16 m = __float2bfloat16(r1);
        float r2 = r1 - __bfloat162float(m);
        g_xhi[i0] = h; g_xmid[i0] = m; g_xlo[i0] = __float2bfloat16(r2);
        h = __float2bfloat16(b);
        r1 = b - __bfloat162float(h);
        m = __float2bfloat16(r1);
        r2 = r1 - __bfloat162float(m);
        g_xhi[i1] = h; g_xmid[i1] = m; g_xlo[i1] = __float2bfloat16(r2);
    }

    float s = a * a + b * b;
#pragma unroll
    for (int o = 16; o; o >>= 1) s += __shfl_xor_sync(0xffffffffu, s, o);
    if (lane == 0) g_ninv[warp] = 1.0f / sqrtf(s);
}

__device__ __forceinline__ void push_cand(int r, int c, float v) {
    int slot = atomicAdd(&g_ccnt[r], 1);
    if (slot < CAP)
        g_cand[(size_t)r * CAP + slot] =
            ((unsigned long long)okey(v) << 32) | (unsigned)(~(unsigned)c);
}

// ---------------- similarity via mma.sync HMMA (bf16x3, ~5e-7) — candidate gen --------
// One CTA = 128x128 sim tile. 8 warps (2m x 4n), warp tile 64x32 = 4x4 m16n8k16 frags.
// Triangular grid: bj >= bi computed; off-diag tiles push both (r,c) and (c,r).
#define SIM_SMEM 98304

__global__ void __launch_bounds__(256) sim_tc_kernel() {
    const int bi = blockIdx.y, bj = blockIdx.x;
    if (bj < bi) return;
    extern __shared__ char smem[];
    const uint32_t sb = smem_u32(smem);
    const int tid = threadIdx.x;
    const int wid = tid >> 5, lane = tid & 31;
    const int wm = wid >> 2, wn = wid & 3;

    const __nv_bfloat16* parts[3] = {g_xhi, g_xmid, g_xlo};
    for (int i = tid; i < 3072; i += 256) {
        int p = i >> 10, ci = i & 1023;
        int row = ci >> 3, ch = ci & 7;
        const uint4* s = (const uint4*)(parts[p] + (size_t)(bi * 128 + row) * D + ch * 8);
        *(uint4*)(smem + p * 16384 + swz128((uint32_t)(row * 128 + ch * 16))) = *s;
    }
    for (int i = tid; i < 3072; i += 256) {
        int p = i >> 10, ci = i & 1023;
        int row = ci >> 3, ch = ci & 7;
        const uint4* s = (const uint4*)(parts[p] + (size_t)(bj * 128 + row) * D + ch * 8);
        *(uint4*)(smem + 49152 + p * 16384 + swz128((uint32_t)(row * 128 + ch * 16))) = *s;
    }
    __syncthreads();

    float acc[4][4][4];
#pragma unroll
    for (int im = 0; im < 4; im++)
#pragma unroll
        for (int jn = 0; jn < 4; jn++)
#pragma unroll
            for (int q = 0; q < 4; q++) acc[im][jn][q] = 0.0f;

    const int pa[6] = {0, 0, 1, 0, 2, 1};
    const int pb[6] = {0, 1, 0, 2, 0, 1};

    const int asub = lane >> 3;
    const int arh = asub & 1, akh = asub >> 1;
    const int brh = asub >> 1, bkh = asub & 1;
    const int l7 = lane & 7;

#pragma unroll
    for (int t = 0; t < 6; t++) {
        const uint32_t Ab = sb + pa[t] * 16384;
        const uint32_t Bb = sb + 49152 + pb[t] * 16384;
#pragma unroll
        for (int ks = 0; ks < 4; ks++) {
            uint32_t af[4][4];
#pragma unroll
            for (int im = 0; im < 4; im++) {
                int row = wm * 64 + im * 16 + arh * 8 + l7;
                ldm4(af[im], Ab + swz128((uint32_t)(row * 128 + ks * 32 + akh * 16)));
            }
            uint32_t bfr[2][4];
#pragma unroll
            for (int jp = 0; jp < 2; jp++) {
                int nrow = wn * 32 + (jp * 2 + brh) * 8 + l7;
                ldm4(bfr[jp], Bb + swz128((uint32_t)(nrow * 128 + ks * 32 + bkh * 16)));
            }
#pragma unroll
            for (int im = 0; im < 4; im++)
#pragma unroll
                for (int jn = 0; jn < 4; jn++)
                    mma_bf16(acc[im][jn], af[im], &bfr[jn >> 1][(jn & 1) * 2]);
        }
    }

    float irv[4][2], icv[4][2];
#pragma unroll
    for (int im = 0; im < 4; im++) {
        int R0 = bi * 128 + wm * 64 + im * 16 + (lane >> 2);
        irv[im][0] = g_ninv[R0];
        irv[im][1] = g_ninv[R0 + 8];
    }
#pragma unroll
    for (int jn = 0; jn < 4; jn++) {
        int C0 = bj * 128 + wn * 32 + jn * 8 + (lane & 3) * 2;
        icv[jn][0] = g_ninv[C0];
        icv[jn][1] = g_ninv[C0 + 1];
    }
    const bool diag = (bi == bj);
#pragma unroll
    for (int im = 0; im < 4; im++) {
        int R0 = bi * 128 + wm * 64 + im * 16 + (lane >> 2);
#pragma unroll
        for (int jn = 0; jn < 4; jn++) {
            int C0 = bj * 128 + wn * 32 + jn * 8 + (lane & 3) * 2;
#pragma unroll
            for (int q = 0; q < 4; q++) {
                int R = R0 + (q >> 1) * 8;
                int C = C0 + (q & 1);
                float v = acc[im][jn][q] * irv[im][q >> 1] * icv[jn][q & 1];
                if (v > CAND_THR) {
                    push_cand(R, C, v);
                    if (!diag) push_cand(C, R, v);
                }
            }
        }
    }
}

// ---------------- top-17: approx top-24 -> exact fp32 re-rank (proven ordering) -------
// Per row: select 24 best approx candidates, recompute each exactly with the
// sequential fp32 dot (same arithmetic as the previously-passing kernels),
// select top-17 by exact value. Sound exclusion check: every excluded candidate
// has exact <= approx_rank23 + eps < exact_rank16  =>  subset top-17 == global.
__global__ void topk_cand_kernel(const float* __restrict__ x,
                                 float* o_ei0, float* o_ei1, float* o_ew) {
    __shared__ float xrow[8][64];
    const int warp = threadIdx.x >> 5;
    const int lane = threadIdx.x & 31;
    const int r = blockIdx.x * 8 + warp;
    int cnt = g_ccnt[r];
    if (cnt < 17 || cnt > CAP) {
        if (lane == 0) g_bad[r] = 1;
        return;
    }
    const unsigned long long* base = g_cand + (size_t)r * CAP;
    unsigned long long k[16];
#pragma unroll
    for (int j = 0; j < 16; j++) {
        int idx = lane + (j << 5);
        k[j] = (idx < cnt) ? base[idx] : 0ull;
    }
    unsigned long long best = k[0];
#pragma unroll
    for (int j = 1; j < 16; j++) if (k[j] > best) best = k[j];

    // approx top-24: lane l keeps approx rank-l key
    const int T = cnt < 24 ? cnt : 24;
    unsigned long long sel = 0ull;
    for (int t = 0; t < 24; t++) {
        if (t >= T) break;
        unsigned long long m = best;
#pragma unroll
        for (int off = 16; off; off >>= 1) {
            unsigned long long o = __shfl_xor_sync(0xffffffffu, m, off);
            if (o > m) m = o;
        }
        if (t == lane) sel = m;
        if (best == m) {
#pragma unroll
            for (int j = 0; j < 16; j++) if (k[j] == m) k[j] = 0ull;
            best = k[0];
#pragma unroll
            for (int j = 1; j < 16; j++) if (k[j] > best) best = k[j];
        }
    }

    // row vector to shared (warp-private)
    xrow[warp][lane]      = x[(size_t)r * D + lane];
    xrow[warp][lane + 32] = x[(size_t)r * D + lane + 32];
    __syncwarp();

    // exact sequential fp32 recompute for lanes 0..T-1
    unsigned long long ekey = 0ull;
    float aval = -2.0f;
    unsigned cidx = 0;
    if (lane < T) {
        cidx = ~((unsigned)sel);
        aval = iokey((unsigned)(sel >> 32));
        const float4* xc4 = (const float4*)(x + (size_t)cidx * D);
        float dot = 0.0f;
#pragma unroll
        for (int q = 0; q < 16; q++) {
            float4 v = xc4[q];
            dot = fmaf(v.x, xrow[warp][q * 4 + 0], dot);
            dot = fmaf(v.y, xrow[warp][q * 4 + 1], dot);
            dot = fmaf(v.z, xrow[warp][q * 4 + 2], dot);
            dot = fmaf(v.w, xrow[warp][q * 4 + 3], dot);
        }
        float ve = dot * g_ninv[r] * g_ninv[cidx];
        ekey = ((unsigned long long)okey(ve) << 32) | (unsigned)(~cidx);
    }

    // exact top-17 among the (<=24) exact keys; lane l keeps rank l+1
    unsigned long long eb = ekey;
    unsigned long long mine = 0ull;
    for (int t = 0; t < 17; t++) {
        unsigned long long m = eb;
#pragma unroll
        for (int off = 16; off; off >>= 1) {
            unsigned long long o = __shfl_xor_sync(0xffffffffu, m, off);
            if (o > m) m = o;
        }
        if (t == lane + 1) mine = m;
        if (lane == 15 && t == 16) mine = m;   // lane15 also rank16? no: t==16 == lane+1 for lane 15
        if (eb == m) eb = 0ull;
    }

    // soundness check when candidates were excluded (cnt > 24)
    unsigned long long m15 = __shfl_sync(0xffffffffu, mine, 15);
    float e16v = iokey((unsigned)(m15 >> 32));
    float a23 = __shfl_sync(0xffffffffu, aval, 23);
    if (cnt > 24 && e16v < a23 + 2e-5f) {
        if (lane == 0) g_bad[r] = 1;
        return;
    }

    if (lane < 16) {
        unsigned idx = ~((unsigned)mine);
        float val = iokey((unsigned)(mine >> 32));
        float w = (val > 0.5f) ? val : 0.0f;
        int e = r * KNB + lane;
        g_edst[e] = (int)idx;
        g_ew[e]   = w;
        if (w > 0.0f) atomicAdd(&g_cnt[(int)idx], 1);
        if (o_ei0) {
            o_ei0[e] = (float)r;
            o_ei1[e] = (float)idx;
            o_ew[e]  = w;
        }
    }
}

// ---------------- fallback: exact fp32 full-row recompute for flagged rows ------------
__global__ void fallback_kernel(const float* __restrict__ x,
                                float* o_ei0, float* o_ei1, float* o_ew) {
    __shared__ float xr[64];
    __shared__ float snv;
    __shared__ unsigned long long keys[256];
    __shared__ unsigned long long wins[17];
    const int t = threadIdx.x;
    const int r0 = blockIdx.x * 64;

    int flag = (t < 64) ? g_bad[r0 + t] : 0;
    if (__syncthreads_or(flag) == 0) return;

    for (int rr = 0; rr < 64; rr++) {
        int r = r0 + rr;
        if (g_bad[r] == 0) continue;
        if (t < 64) xr[t] = x[(size_t)r * D + t];
        if (t == 0) snv = g_ninv[r];
        __syncthreads();

        unsigned long long k[32];
#pragma unroll 1
        for (int j = 0; j < 32; j++) {
            int c = t + (j << 8);
            const float* xc = x + (size_t)c * D;
            float dot = 0.0f;
            for (int d = 0; d < 64; d++) dot = fmaf(xc[d], xr[d], dot);
            float v = dot * snv * g_ninv[c];
            k[j] = ((unsigned long long)okey(v) << 32) | (unsigned)(~(unsigned)c);
        }
        unsigned long long m = k[0];
#pragma unroll
        for (int j = 1; j < 32; j++) if (k[j] > m) m = k[j];
        keys[t] = m;
        __syncthreads();

        for (int kk = 0; kk < 17; kk++) {
            if (t < 32) {
                unsigned long long mm = keys[t];
#pragma unroll
                for (int w = 1; w < 8; w++) {
                    unsigned long long o = keys[t + (w << 5)];
                    if (o > mm) mm = o;
                }
#pragma unroll
                for (int off = 16; off; off >>= 1) {
                    unsigned long long o = __shfl_xor_sync(0xffffffffu, mm, off);
                    if (o > mm) mm = o;
                }
                if (t == 0) wins[kk] = mm;
            }
            __syncthreads();
            unsigned long long wk = wins[kk];
            unsigned widx = ~((unsigned)wk);
            if ((int)(widx & 255) == t) {
#pragma unroll
                for (int j = 0; j < 32; j++) if (k[j] == wk) k[j] = 0ull;
                unsigned long long mm = k[0];
#pragma unroll
                for (int j = 1; j < 32; j++) if (k[j] > mm) mm = k[j];
                keys[t] = mm;
            }
            __syncthreads();
        }

        if (t >= 1 && t < 17) {
            unsigned long long wk = wins[t];
            unsigned idx = ~((unsigned)wk);
            float val = iokey((unsigned)(wk >> 32));
            float w = (val > 0.5f) ? val : 0.0f;
            int e = r * KNB + (t - 1);
            g_edst[e] = (int)idx;
            g_ew[e]   = w;
            if (w > 0.0f) atomicAdd(&g_cnt[(int)idx], 1);
            if (o_ei0) {
                o_ei0[e] = (float)r;
                o_ei1[e] = (float)idx;
                o_ew[e]  = w;
            }
        }
        __syncthreads();
    }
}

// ---------------- CSR-by-dst build (deterministic) ------------
__global__ void scan_kernel() {   // 1 block, 1024 threads, 8 elems each
    __shared__ int ss[1024];
    int t = threadIdx.x;
    int base = t * 8;
    int loc[8];
    int s = 0;
#pragma unroll
    for (int j = 0; j < 8; j++) { loc[j] = s; s += g_cnt[base + j]; }
    ss[t] = s;
    __syncthreads();
    for (int d = 1; d < 1024; d <<= 1) {
        int v = (t >= d) ? ss[t - d] : 0;
        __syncthreads();
        ss[t] += v;
        __syncthreads();
    }
    int excl = (t == 0) ? 0 : ss[t - 1];
#pragma unroll
    for (int j = 0; j < 8; j++) g_off[base + j] = excl + loc[j];
    if (t == 1023) g_off[N] = ss[1023];
}

__global__ void fill_kernel() {
    int e = blockIdx.x * blockDim.x + threadIdx.x;
    if (e < E && g_ew[e] > 0.0f) {
        int d = g_edst[e];
        int slot = atomicAdd(&g_fill[d], 1);
        g_inc[g_off[d] + slot] = e;
    }
}

// sort each bucket by edge id (canonical order), then deterministic deg
__global__ void sortdeg_kernel() {
    int d = blockIdx.x * blockDim.x + threadIdx.x;
    if (d >= N) return;
    int s = g_off[d], e = g_off[d + 1];
    for (int i = s + 1; i < e; i++) {
        int key = g_inc[i];
        int j = i - 1;
        while (j >= s && g_inc[j] > key) { g_inc[j + 1] = g_inc[j]; j--; }
        g_inc[j + 1] = key;
    }
    float deg = 2.0f;   // graph self-loop (w=1) + gcn self-loop (w=1)
    for (int i = s; i < e; i++) deg += g_ew[g_inc[i]];
    g_dinv[d] = 1.0f / sqrtf(deg);
}

// ---------------- small dense GEMM: C[N][FOUT] = A[N][FIN] @ W (+bias) ----------------
template <int FIN, int FOUT, int NB>
__global__ void gemm_kernel(const float* __restrict__ A, const float* __restrict__ W,
                            const float* __restrict__ bias, float* __restrict__ C) {
    __shared__ float As[NB][FIN];
    __shared__ float Ws[FIN * FOUT];
    const int t = threadIdx.x;        // FOUT threads
    const int n0 = blockIdx.x * NB;
    for (int i = t; i < NB * FIN; i += FOUT) As[i / FIN][i % FIN] = A[(size_t)n0 * FIN + i];
    for (int i = t; i < FIN * FOUT; i += FOUT) Ws[i] = W[i];
    __syncthreads();
#pragma unroll 1
    for (int n = 0; n < NB; n++) {
        float acc = bias ? bias[t] : 0.0f;
#pragma unroll
        for (int d = 0; d < FIN; d++) acc = fmaf(As[n][d], Ws[d * FOUT + t], acc);
        C[(size_t)(n0 + n) * FOUT + t] = acc;
    }
}

// ---------------- fused gather + bias + relu + LayerNorm (deterministic) ----------
template <int F>
__global__ void gather_epi_kernel(const float* __restrict__ h, const float* __restrict__ b,
                                  const float* __restrict__ g, const float* __restrict__ be,
                                  float* __restrict__ y) {
    const int n = blockIdx.x;
    const int f = threadIdx.x;
    __shared__ float s1[F / 32];
    __shared__ float s2[F / 32];

    int s = g_off[n], e = g_off[n + 1];
    float di = g_dinv[n];
    float acc = 0.0f;
    for (int i = s; i < e; i++) {
        int eid = g_inc[i];
        int src = eid >> 4;
        acc = fmaf(g_ew[eid] * g_dinv[src], h[(size_t)src * F + f], acc);
    }
    float v = acc * di + 2.0f * di * di * h[(size_t)n * F + f] + b[f];
    v = fmaxf(v, 0.0f);

    float sv = v;
#pragma unroll
    for (int o = 16; o; o >>= 1) sv += __shfl_xor_sync(0xffffffffu, sv, o);
    if ((f & 31) == 0) s1[f >> 5] = sv;
    __syncthreads();
    float tot = 0.0f;
#pragma unroll
    for (int i = 0; i < F / 32; i++) tot += s1[i];
    float mu = tot / (float)F;

    float dv = v - mu;
    float sq = dv * dv;
#pragma unroll
    for (int o = 16; o; o >>= 1) sq += __shfl_xor_sync(0xffffffffu, sq, o);
    if ((f & 31) == 0) s2[f >> 5] = sq;
    __syncthreads();
    float tot2 = 0.0f;
#pragma unroll
    for (int i = 0; i < F / 32; i++) tot2 += s2[i];
    float var = tot2 / (float)F;

    y[(size_t)n * F + f] = dv * (1.0f / sqrtf(var + 1e-5f)) * g[f] + be[f];
}

// ---------------- launch ----------------
extern "C" void kernel_launch(void* const* d_in, const int* in_sizes, int n_in,
                              void* d_out, int out_size) {
    const float* x   = (const float*)d_in[0];
    const float* W1  = (const float*)d_in[1];
    const float* b1  = (const float*)d_in[2];
    const float* g1  = (const float*)d_in[3];
    const float* be1 = (const float*)d_in[4];
    const float* W2  = (const float*)d_in[5];
    const float* b2  = (const float*)d_in[6];
    const float* g2  = (const float*)d_in[7];
    const float* be2 = (const float*)d_in[8];
    const float* Wp  = (const float*)d_in[9];
    const float* bp  = (const float*)d_in[10];

    float* o = (float*)d_out;
    const int OUT_ELEMS = N * D;                  // 524288
    const int E_TOTAL = E + N;                    // 139264
    const int FULL = OUT_ELEMS + 3 * E_TOTAL;     // 942080

    float* o_out = nullptr;
    float* o_ei0 = nullptr;
    float* o_ei1 = nullptr;
    float* o_ew  = nullptr;
    if (out_size >= OUT_ELEMS) o_out = o;
    if (out_size >= FULL) {
        o_ei0 = o + OUT_ELEMS;
        o_ei1 = o_ei0 + E_TOTAL;
        o_ew  = o_ei1 + E_TOTAL;
    }

    cudaFuncSetAttribute(sim_tc_kernel,
                         cudaFuncAttributeMaxDynamicSharedMemorySize, SIM_SMEM);

    norm_init_kernel<<<(N * 32) / 256, 256>>>(x, o_ei0, o_ei1, o_ew);
    sim_tc_kernel<<<dim3(N / 128, N / 128), 256, SIM_SMEM>>>();
    topk_cand_kernel<<<N / 8, 256>>>(x, o_ei0, o_ei1, o_ew);
    fallback_kernel<<<N / 64, 256>>>(x, o_ei0, o_ei1, o_ew);

    scan_kernel<<<1, 1024>>>();
    fill_kernel<<<E / 256, 256>>>();
    sortdeg_kernel<<<(N + 255) / 256, 256>>>();

    // layer 1
    gemm_kernel<D, H1, 16><<<N / 16, H1>>>(x, W1, nullptr, g_h1);
    gather_epi_kernel<H1><<<N, H1>>>(g_h1, b1, g1, be1, g_y1);

    // layer 2
    gemm_kernel<H1, H2, 16><<<N / 16, H2>>>(g_y1, W2, nullptr, g_h2);
    gather_epi_kernel<H2><<<N, H2>>>(g_h2, b2, g2, be2, g_y2);

    // projection (+bias) straight into output
    if (o_out)
        gemm_kernel<H2, D, 16><<<N / 16, D>>>(g_y2, Wp, bp, o_out);
}

// round 17
// speedup vs baseline: 1.0746x; 1.0746x over previous
#include <cuda_runtime.h>
#include <cuda_bf16.h>
#include <math.h>
#include <stdint.h>

#define N 8192
#define D 64
#define H1 128
#define H2 64
#define KNB 16            // kept neighbors per row (rank 0 = self, dropped)
#define E (N * KNB)       // 131072 fixed edge slots, src(e) = e >> 4
#define CAP 512           // candidate slots per row
#define CAND_THR 0.25f    // prefilter threshold on approx sims (17th max ~ 0.36)

// ---------------- device scratch (no allocations allowed) ----------------
__device__ unsigned long long g_cand[(size_t)N * CAP];  // 32 MB candidate keys
__device__ int   g_ccnt[N];
__device__ int   g_bad[N];
__device__ float g_ninv[N];                // 1/||x_i||
__device__ float g_dinv[N];
__device__ int   g_edst[E];
__device__ float g_ew[E];
__device__ int   g_cnt[N];
__device__ int   g_fill[N];
__device__ int   g_off[N + 1];
__device__ int   g_inc[E];                 // CSR-by-dst edge ids (sorted per bucket)
__device__ float g_h1[(size_t)N * H1];
__device__ float g_y1[(size_t)N * H1];
__device__ float g_h2[(size_t)N * H2];
__device__ float g_y2[(size_t)N * H2];
__device__ int   g_dummy;
// bf16x2 split of x (hi + mid reconstructs fp32 to ~2^-17; exact re-rank fixes order)
__device__ __nv_bfloat16 g_xhi[(size_t)N * D];
__device__ __nv_bfloat16 g_xmid[(size_t)N * D];

// order-preserving float <-> uint key (ascending)
__device__ __forceinline__ unsigned okey(float v) {
    unsigned u = __float_as_uint(v);
    return u ^ (((unsigned)((int)u >> 31)) | 0x80000000u);
}
__device__ __forceinline__ float iokey(unsigned u) {
    return __uint_as_float(u ^ ((~((unsigned)((int)u >> 31))) | 0x80000000u));
}

__device__ __forceinline__ uint32_t smem_u32(const void* p) {
    uint32_t a;
    asm("{ .reg .u64 t; cvta.to.shared.u64 t, %1; cvt.u32.u64 %0, t; }" : "=r"(a) : "l"(p));
    return a;
}
__device__ __forceinline__ uint32_t swz128(uint32_t off) {
    return off ^ ((off >> 3) & 0x70);
}
__device__ __forceinline__ void ldm4(uint32_t* r, uint32_t addr) {
    asm volatile("ldmatrix.sync.aligned.m8n8.x4.shared.b16 {%0,%1,%2,%3}, [%4];"
                 : "=r"(r[0]), "=r"(r[1]), "=r"(r[2]), "=r"(r[3]) : "r"(addr));
}
__device__ __forceinline__ void mma_bf16(float* c, const uint32_t* a, const uint32_t* b) {
    asm volatile("mma.sync.aligned.m16n8k16.row.col.f32.bf16.bf16.f32 "
                 "{%0,%1,%2,%3}, {%4,%5,%6,%7}, {%8,%9}, {%0,%1,%2,%3};"
                 : "+f"(c[0]), "+f"(c[1]), "+f"(c[2]), "+f"(c[3])
                 : "r"(a[0]), "r"(a[1]), "r"(a[2]), "r"(a[3]), "r"(b[0]), "r"(b[1]));
}

// ---------------- fused norms + init + bf16x2 split ----------------
__global__ void norm_init_kernel(const float* __restrict__ x,
                                 float* o_ei0, float* o_ei1, float* o_ew) {
    int gi = blockIdx.x * blockDim.x + threadIdx.x;
    if (gi < N) {
        g_ccnt[gi] = 0;
        g_bad[gi]  = 0;
        g_cnt[gi]  = 0;
        g_fill[gi] = 0;
        if (o_ei0) {
            size_t p = (size_t)E + gi;
            o_ei0[p] = (float)gi;
            o_ei1[p] = (float)gi;
            o_ew[p]  = 1.0f;
        }
    }
    int warp = gi >> 5;
    int lane = threadIdx.x & 31;
    if (warp >= N) return;
    const float* row = x + (size_t)warp * D;
    float a = row[lane], b = row[lane + 32];

    size_t i0 = (size_t)warp * D + lane;
    size_t i1 = i0 + 32;
    {
        __nv_bfloat16 h = __float2bfloat16(a);
        g_xhi[i0] = h;
        g_xmid[i0] = __float2bfloat16(a - __bfloat162float(h));
        h = __float2bfloat16(b);
        g_xhi[i1] = h;
        g_xmid[i1] = __float2bfloat16(b - __bfloat162float(h));
    }

    float s = a * a + b * b;
#pragma unroll
    for (int o = 16; o; o >>= 1) s += __shfl_xor_sync(0xffffffffu, s, o);
    if (lane == 0) g_ninv[warp] = 1.0f / sqrtf(s);
}

__global__ void noop_kernel() {
    if (blockIdx.x == 0 && threadIdx.x == 0) g_dummy = 0;
}

__device__ __forceinline__ void push_cand(int r, int c, float v) {
    int slot = atomicAdd(&g_ccnt[r], 1);
    if (slot < CAP)
        g_cand[(size_t)r * CAP + slot] =
            ((unsigned long long)okey(v) << 32) | (unsigned)(~(unsigned)c);
}

// ---------------- similarity via mma.sync HMMA (bf16x2, 3 passes, ~1e-5) --------------
// Candidate generator only: final ordering comes from exact fp32 re-rank.
// One CTA = 128x128 tile, 8 warps (2m x 4n), warp tile 64x32 = 4x4 m16n8k16 frags.
// Triangular grid (bj >= bi); off-diag tiles push both (r,c) and (c,r).
// Dynamic smem 64KB: A planes [2][128x64bf16 SW128] @0, B planes @32768.
#define SIM_SMEM 65536

__global__ void __launch_bounds__(256) sim_tc_kernel() {
    const int bi = blockIdx.y, bj = blockIdx.x;
    if (bj < bi) return;
    extern __shared__ char smem[];
    const uint32_t sb = smem_u32(smem);
    const int tid = threadIdx.x;
    const int wid = tid >> 5, lane = tid & 31;
    const int wm = wid >> 2, wn = wid & 3;

    const __nv_bfloat16* parts[2] = {g_xhi, g_xmid};
#pragma unroll
    for (int p = 0; p < 2; p++) {
        for (int i = tid; i < 1024; i += 256) {
            int row = i >> 3, ch = i & 7;
            const uint4* s = (const uint4*)(parts[p] + (size_t)(bi * 128 + row) * D + ch * 8);
            *(uint4*)(smem + p * 16384 + swz128((uint32_t)(row * 128 + ch * 16))) = *s;
        }
        for (int i = tid; i < 1024; i += 256) {
            int row = i >> 3, ch = i & 7;
            const uint4* s = (const uint4*)(parts[p] + (size_t)(bj * 128 + row) * D + ch * 8);
            *(uint4*)(smem + 32768 + p * 16384 + swz128((uint32_t)(row * 128 + ch * 16))) = *s;
        }
    }
    __syncthreads();

    float acc[4][4][4];
#pragma unroll
    for (int im = 0; im < 4; im++)
#pragma unroll
        for (int jn = 0; jn < 4; jn++)
#pragma unroll
            for (int q = 0; q < 4; q++) acc[im][jn][q] = 0.0f;

    const int pa[3] = {0, 0, 1};
    const int pb[3] = {0, 1, 0};

    const int asub = lane >> 3;
    const int arh = asub & 1, akh = asub >> 1;
    const int brh = asub >> 1, bkh = asub & 1;
    const int l7 = lane & 7;

#pragma unroll
    for (int t = 0; t < 3; t++) {
        const uint32_t Ab = sb + pa[t] * 16384;
        const uint32_t Bb = sb + 32768 + pb[t] * 16384;
#pragma unroll
        for (int ks = 0; ks < 4; ks++) {
            uint32_t af[4][4];
#pragma unroll
            for (int im = 0; im < 4; im++) {
                int row = wm * 64 + im * 16 + arh * 8 + l7;
                ldm4(af[im], Ab + swz128((uint32_t)(row * 128 + ks * 32 + akh * 16)));
            }
            uint32_t bfr[2][4];
#pragma unroll
            for (int jp = 0; jp < 2; jp++) {
                int nrow = wn * 32 + (jp * 2 + brh) * 8 + l7;
                ldm4(bfr[jp], Bb + swz128((uint32_t)(nrow * 128 + ks * 32 + bkh * 16)));
            }
#pragma unroll
            for (int im = 0; im < 4; im++)
#pragma unroll
                for (int jn = 0; jn < 4; jn++)
                    mma_bf16(acc[im][jn], af[im], &bfr[jn >> 1][(jn & 1) * 2]);
        }
    }

    float irv[4][2], icv[4][2];
#pragma unroll
    for (int im = 0; im < 4; im++) {
        int R0 = bi * 128 + wm * 64 + im * 16 + (lane >> 2);
        irv[im][0] = g_ninv[R0];
        irv[im][1] = g_ninv[R0 + 8];
    }
#pragma unroll
    for (int jn = 0; jn < 4; jn++) {
        int C0 = bj * 128 + wn * 32 + jn * 8 + (lane & 3) * 2;
        icv[jn][0] = g_ninv[C0];
        icv[jn][1] = g_ninv[C0 + 1];
    }
    const bool diag = (bi == bj);
#pragma unroll
    for (int im = 0; im < 4; im++) {
        int R0 = bi * 128 + wm * 64 + im * 16 + (lane >> 2);
#pragma unroll
        for (int jn = 0; jn < 4; jn++) {
            int C0 = bj * 128 + wn * 32 + jn * 8 + (lane & 3) * 2;
#pragma unroll
            for (int q = 0; q < 4; q++) {
                int R = R0 + (q >> 1) * 8;
                int C = C0 + (q & 1);
                float v = acc[im][jn][q] * irv[im][q >> 1] * icv[jn][q & 1];
                if (v > CAND_THR) {
                    push_cand(R, C, v);
                    if (!diag) push_cand(C, R, v);
                }
            }
        }
    }
}

// ---------------- top-17: approx top-24 -> exact fp32 re-rank (proven ordering) -------
__global__ void topk_cand_kernel(const float* __restrict__ x,
                                 float* o_ei0, float* o_ei1, float* o_ew) {
    __shared__ float xrow[8][64];
    const int warp = threadIdx.x >> 5;
    const int lane = threadIdx.x & 31;
    const int r = blockIdx.x * 8 + warp;
    int cnt = g_ccnt[r];
    if (cnt < 17 || cnt > CAP) {
        if (lane == 0) g_bad[r] = 1;
        return;
    }
    const unsigned long long* base = g_cand + (size_t)r * CAP;
    unsigned long long k[16];
#pragma unroll
    for (int j = 0; j < 16; j++) {
        int idx = lane + (j << 5);
        k[j] = (idx < cnt) ? base[idx] : 0ull;
    }
    unsigned long long best = k[0];
#pragma unroll
    for (int j = 1; j < 16; j++) if (k[j] > best) best = k[j];

    // approx top-24: lane l keeps approx rank-l key
    const int T = cnt < 24 ? cnt : 24;
    unsigned long long sel = 0ull;
    for (int t = 0; t < 24; t++) {
        if (t >= T) break;
        unsigned long long m = best;
#pragma unroll
        for (int off = 16; off; off >>= 1) {
            unsigned long long o = __shfl_xor_sync(0xffffffffu, m, off);
            if (o > m) m = o;
        }
        if (t == lane) sel = m;
        if (best == m) {
#pragma unroll
            for (int j = 0; j < 16; j++) if (k[j] == m) k[j] = 0ull;
            best = k[0];
#pragma unroll
            for (int j = 1; j < 16; j++) if (k[j] > best) best = k[j];
        }
    }

    xrow[warp][lane]      = x[(size_t)r * D + lane];
    xrow[warp][lane + 32] = x[(size_t)r * D + lane + 32];
    __syncwarp();

    // exact sequential fp32 recompute for lanes 0..T-1
    unsigned long long ekey = 0ull;
    float aval = -2.0f;
    if (lane < T) {
        unsigned cidx = ~((unsigned)sel);
        aval = iokey((unsigned)(sel >> 32));
        const float4* xc4 = (const float4*)(x + (size_t)cidx * D);
        float dot = 0.0f;
#pragma unroll
        for (int q = 0; q < 16; q++) {
            float4 v = xc4[q];
            dot = fmaf(v.x, xrow[warp][q * 4 + 0], dot);
            dot = fmaf(v.y, xrow[warp][q * 4 + 1], dot);
            dot = fmaf(v.z, xrow[warp][q * 4 + 2], dot);
            dot = fmaf(v.w, xrow[warp][q * 4 + 3], dot);
        }
        float ve = dot * g_ninv[r] * g_ninv[cidx];
        ekey = ((unsigned long long)okey(ve) << 32) | (unsigned)(~cidx);
    }

    // exact top-17 among the (<=24) exact keys; lane l keeps rank l+1
    unsigned long long eb = ekey;
    unsigned long long mine = 0ull;
    for (int t = 0; t < 17; t++) {
        unsigned long long m = eb;
#pragma unroll
        for (int off = 16; off; off >>= 1) {
            unsigned long long o = __shfl_xor_sync(0xffffffffu, m, off);
            if (o > m) m = o;
        }
        if (t == lane + 1) mine = m;
        if (eb == m) eb = 0ull;
    }

    // sound exclusion check (only matters when candidates were cut at 24)
    unsigned long long m15 = __shfl_sync(0xffffffffu, mine, 15);
    float e16v = iokey((unsigned)(m15 >> 32));
    float a23 = __shfl_sync(0xffffffffu, aval, 23);
    if (cnt > 24 && e16v < a23 + 1e-4f) {
        if (lane == 0) g_bad[r] = 1;
        return;
    }

    if (lane < 16) {
        unsigned idx = ~((unsigned)mine);
        float val = iokey((unsigned)(mine >> 32));
        float w = (val > 0.5f) ? val : 0.0f;
        int e = r * KNB + lane;
        g_edst[e] = (int)idx;
        g_ew[e]   = w;
        if (w > 0.0f) atomicAdd(&g_cnt[(int)idx], 1);
        if (o_ei0) {
            o_ei0[e] = (float)r;
            o_ei1[e] = (float)idx;
            o_ew[e]  = w;
        }
    }
}

// ---------------- fallback: exact fp32 full-row recompute for flagged rows ------------
__global__ void fallback_kernel(const float* __restrict__ x,
                                float* o_ei0, float* o_ei1, float* o_ew) {
    __shared__ float xr[64];
    __shared__ float snv;
    __shared__ unsigned long long keys[256];
    __shared__ unsigned long long wins[17];
    const int t = threadIdx.x;
    const int r0 = blockIdx.x * 64;

    int flag = (t < 64) ? g_bad[r0 + t] : 0;
    if (__syncthreads_or(flag) == 0) return;

    for (int rr = 0; rr < 64; rr++) {
        int r = r0 + rr;
        if (g_bad[r] == 0) continue;
        if (t < 64) xr[t] = x[(size_t)r * D + t];
        if (t == 0) snv = g_ninv[r];
        __syncthreads();

        unsigned long long k[32];
#pragma unroll 1
        for (int j = 0; j < 32; j++) {
            int c = t + (j << 8);
            const float* xc = x + (size_t)c * D;
            float dot = 0.0f;
            for (int d = 0; d < 64; d++) dot = fmaf(xc[d], xr[d], dot);
            float v = dot * snv * g_ninv[c];
            k[j] = ((unsigned long long)okey(v) << 32) | (unsigned)(~(unsigned)c);
        }
        unsigned long long m = k[0];
#pragma unroll
        for (int j = 1; j < 32; j++) if (k[j] > m) m = k[j];
        keys[t] = m;
        __syncthreads();

        for (int kk = 0; kk < 17; kk++) {
            if (t < 32) {
                unsigned long long mm = keys[t];
#pragma unroll
                for (int w = 1; w < 8; w++) {
                    unsigned long long o = keys[t + (w << 5)];
                    if (o > mm) mm = o;
                }
#pragma unroll
                for (int off = 16; off; off >>= 1) {
                    unsigned long long o = __shfl_xor_sync(0xffffffffu, mm, off);
                    if (o > mm) mm = o;
                }
                if (t == 0) wins[kk] = mm;
            }
            __syncthreads();
            unsigned long long wk = wins[kk];
            unsigned widx = ~((unsigned)wk);
            if ((int)(widx & 255) == t) {
#pragma unroll
                for (int j = 0; j < 32; j++) if (k[j] == wk) k[j] = 0ull;
                unsigned long long mm = k[0];
#pragma unroll
                for (int j = 1; j < 32; j++) if (k[j] > mm) mm = k[j];
                keys[t] = mm;
            }
            __syncthreads();
        }

        if (t >= 1 && t < 17) {
            unsigned long long wk = wins[t];
            unsigned idx = ~((unsigned)wk);
            float val = iokey((unsigned)(wk >> 32));
            float w = (val > 0.5f) ? val : 0.0f;
            int e = r * KNB + (t - 1);
            g_edst[e] = (int)idx;
            g_ew[e]   = w;
            if (w > 0.0f) atomicAdd(&g_cnt[(int)idx], 1);
            if (o_ei0) {
                o_ei0[e] = (float)r;
                o_ei1[e] = (float)idx;
                o_ew[e]  = w;
            }
        }
        __syncthreads();
    }
}

// ---------------- CSR-by-dst build (deterministic) ------------
__global__ void scan_kernel() {   // 1 block, 1024 threads, 8 elems each
    __shared__ int ss[1024];
    int t = threadIdx.x;
    int base = t * 8;
    int loc[8];
    int s = 0;
#pragma unroll
    for (int j = 0; j < 8; j++) { loc[j] = s; s += g_cnt[base + j]; }
    ss[t] = s;
    __syncthreads();
    for (int d = 1; d < 1024; d <<= 1) {
        int v = (t >= d) ? ss[t - d] : 0;
        __syncthreads();
        ss[t] += v;
        __syncthreads();
    }
    int excl = (t == 0) ? 0 : ss[t - 1];
#pragma unroll
    for (int j = 0; j < 8; j++) g_off[base + j] = excl + loc[j];
    if (t == 1023) g_off[N] = ss[1023];
}

__global__ void fill_kernel() {
    int e = blockIdx.x * blockDim.x + threadIdx.x;
    if (e < E && g_ew[e] > 0.0f) {
        int d = g_edst[e];
        int slot = atomicAdd(&g_fill[d], 1);
        g_inc[g_off[d] + slot] = e;
    }
}

// sort each bucket by edge id (canonical order), then deterministic deg
__global__ void sortdeg_kernel() {
    int d = blockIdx.x * blockDim.x + threadIdx.x;
    if (d >= N) return;
    int s = g_off[d], e = g_off[d + 1];
    for (int i = s + 1; i < e; i++) {
        int key = g_inc[i];
        int j = i - 1;
        while (j >= s && g_inc[j] > key) { g_inc[j + 1] = g_inc[j]; j--; }
        g_inc[j + 1] = key;
    }
    float deg = 2.0f;   // graph self-loop (w=1) + gcn self-loop (w=1)
    for (int i = s; i < e; i++) deg += g_ew[g_inc[i]];
    g_dinv[d] = 1.0f / sqrtf(deg);
}

// ---------------- small dense GEMM: C[N][FOUT] = A[N][FIN] @ W (+bias) ----------------
template <int FIN, int FOUT, int NB>
__global__ void gemm_kernel(const float* __restrict__ A, const float* __restrict__ W,
                            const float* __restrict__ bias, float* __restrict__ C) {
    __shared__ float As[NB][FIN];
    __shared__ float Ws[FIN * FOUT];
    const int t = threadIdx.x;        // FOUT threads
    const int n0 = blockIdx.x * NB;
    for (int i = t; i < NB * FIN; i += FOUT) As[i / FIN][i % FIN] = A[(size_t)n0 * FIN + i];
    for (int i = t; i < FIN * FOUT; i += FOUT) Ws[i] = W[i];
    __syncthreads();
#pragma unroll 1
    for (int n = 0; n < NB; n++) {
        float acc = bias ? bias[t] : 0.0f;
#pragma unroll
        for (int d = 0; d < FIN; d++) acc = fmaf(As[n][d], Ws[d * FOUT + t], acc);
        C[(size_t)(n0 + n) * FOUT + t] = acc;
    }
}

// ---------------- fused gather + bias + relu + LayerNorm (deterministic) ----------
template <int F>
__global__ void gather_epi_kernel(const float* __restrict__ h, const float* __restrict__ b,
                                  const float* __restrict__ g, const float* __restrict__ be,
                                  float* __restrict__ y) {
    const int n = blockIdx.x;
    const int f = threadIdx.x;
    __shared__ float s1[F / 32];
    __shared__ float s2[F / 32];

    int s = g_off[n], e = g_off[n + 1];
    float di = g_dinv[n];
    float acc = 0.0f;
    for (int i = s; i < e; i++) {
        int eid = g_inc[i];
        int src = eid >> 4;
        acc = fmaf(g_ew[eid] * g_dinv[src], h[(size_t)src * F + f], acc);
    }
    float v = acc * di + 2.0f * di * di * h[(size_t)n * F + f] + b[f];
    v = fmaxf(v, 0.0f);

    float sv = v;
#pragma unroll
    for (int o = 16; o; o >>= 1) sv += __shfl_xor_sync(0xffffffffu, sv, o);
    if ((f & 31) == 0) s1[f >> 5] = sv;
    __syncthreads();
    float tot = 0.0f;
#pragma unroll
    for (int i = 0; i < F / 32; i++) tot += s1[i];
    float mu = tot / (float)F;

    float dv = v - mu;
    float sq = dv * dv;
#pragma unroll
    for (int o = 16; o; o >>= 1) sq += __shfl_xor_sync(0xffffffffu, sq, o);
    if ((f & 31) == 0) s2[f >> 5] = sq;
    __syncthreads();
    float tot2 = 0.0f;
#pragma unroll
    for (int i = 0; i < F / 32; i++) tot2 += s2[i];
    float var = tot2 / (float)F;

    y[(size_t)n * F + f] = dv * (1.0f / sqrtf(var + 1e-5f)) * g[f] + be[f];
}

// ---------------- launch ----------------
extern "C" void kernel_launch(void* const* d_in, const int* in_sizes, int n_in,
                              void* d_out, int out_size) {
    const float* x   = (const float*)d_in[0];
    const float* W1  = (const float*)d_in[1];
    const float* b1  = (const float*)d_in[2];
    const float* g1  = (const float*)d_in[3];
    const float* be1 = (const float*)d_in[4];
    const float* W2  = (const float*)d_in[5];
    const float* b2  = (const float*)d_in[6];
    const float* g2  = (const float*)d_in[7];
    const float* be2 = (const float*)d_in[8];
    const float* Wp  = (const float*)d_in[9];
    const float* bp  = (const float*)d_in[10];

    float* o = (float*)d_out;
    const int OUT_ELEMS = N * D;                  // 524288
    const int E_TOTAL = E + N;                    // 139264
    const int FULL = OUT_ELEMS + 3 * E_TOTAL;     // 942080

    float* o_out = nullptr;
    float* o_ei0 = nullptr;
    float* o_ei1 = nullptr;
    float* o_ew  = nullptr;
    if (out_size >= OUT_ELEMS) o_out = o;
    if (out_size >= FULL) {
        o_ei0 = o + OUT_ELEMS;
        o_ei1 = o_ei0 + E_TOTAL;
        o_ew  = o_ei1 + E_TOTAL;
    }

    cudaFuncSetAttribute(sim_tc_kernel,
                         cudaFuncAttributeMaxDynamicSharedMemorySize, SIM_SMEM);

    // launches 1-3: norm/init, layer-1 GEMM (x-only dep), spacer -> sim is #4 for ncu
    norm_init_kernel<<<(N * 32) / 256, 256>>>(x, o_ei0, o_ei1, o_ew);
    gemm_kernel<D, H1, 16><<<N / 16, H1>>>(x, W1, nullptr, g_h1);
    noop_kernel<<<1, 32>>>();
    sim_tc_kernel<<<dim3(N / 128, N / 128), 256, SIM_SMEM>>>();
    topk_cand_kernel<<<N / 8, 256>>>(x, o_ei0, o_ei1, o_ew);
    fallback_kernel<<<N / 64, 256>>>(x, o_ei0, o_ei1, o_ew);

    scan_kernel<<<1, 1024>>>();
    fill_kernel<<<E / 256, 256>>>();
    sortdeg_kernel<<<(N + 255) / 256, 256>>>();

    // layer 1 epilogue (gemm1 already done above)
    gather_epi_kernel<H1><<<N, H1>>>(g_h1, b1, g1, be1, g_y1);

    // layer 2
    gemm_kernel<H1, H2, 16><<<N / 16, H2>>>(g_y1, W2, nullptr, g_h2);
    gather_epi_kernel<H2><<<N, H2>>>(g_h2, b2, g2, be2, g_y2);

    // projection (+bias) straight into output
    if (o_out)
        gemm_kernel<H2, D, 16><<<N / 16, D>>>(g_y2, Wp, bp, o_out);
}